// round 3
// baseline (speedup 1.0000x reference)
#include <cuda_runtime.h>
#include <cuda_bf16.h>

// ---------------------------------------------------------------------------
// Problem constants
// ---------------------------------------------------------------------------
#define BB   128          // batch
#define TT   512          // time steps
#define HH   512          // hidden
#define EE   512          // embed dim
#define VOUT 30000

// output layout (flattened tuple): logits, h1, cw, aw, ccov, acov
#define OFF_H1   (BB * VOUT)                 // 3,840,000
#define OFF_CW   (OFF_H1 + BB * HH)          // 3,905,536
#define OFF_AW   (OFF_CW + BB * TT)          // 3,971,072
#define OFF_CCOV (OFF_AW + BB * TT)          // 4,036,608
#define OFF_ACOV (OFF_CCOV + BB * TT)        // 4,102,144

typedef unsigned long long ull;

// ---------------------------------------------------------------------------
// Scratch (static device globals — no allocation)
// ---------------------------------------------------------------------------
__device__ float g_spart[2][4][BB * TT];   // partial scores per j-tile
__device__ float g_Hh[2][BB * HH];         // h0 @ W1^T + b_attn
__device__ float g_u[2][HH];               // W3 @ Wc
__device__ float g_x[BB * (EE + HH)];      // GRU input [emb, ctx]
__device__ float g_y[BB * (2 * HH)];       // [h1, ctx]
__device__ float g_gi[BB * 3 * HH];
__device__ float g_gh[BB * 3 * HH];

// ---------------------------------------------------------------------------
// f32x2 packed-FMA helpers (FFMA2 — only reachable via PTX fma.rn.f32x2)
// ---------------------------------------------------------------------------
__device__ __forceinline__ ull dup2f(float x) {
    ull r;
    asm("mov.b64 %0, {%1, %1};" : "=l"(r) : "f"(x));
    return r;
}
__device__ __forceinline__ ull ffma2(ull a, ull b, ull c) {
    ull d;
    asm("fma.rn.f32x2 %0, %1, %2, %3;" : "=l"(d) : "l"(a), "l"(b), "l"(c));
    return d;
}
__device__ __forceinline__ float2 unpack2(ull v) {
    float x, y;
    asm("mov.b64 {%0, %1}, %2;" : "=f"(x), "=f"(y) : "l"(v));
    return make_float2(x, y);
}

// ---------------------------------------------------------------------------
// Block reductions
// ---------------------------------------------------------------------------
__device__ __forceinline__ float warpMaxAll(float v) {
    #pragma unroll
    for (int o = 16; o; o >>= 1) v = fmaxf(v, __shfl_xor_sync(0xffffffffu, v, o));
    return v;
}
__device__ __forceinline__ float warpSumAll(float v) {
    #pragma unroll
    for (int o = 16; o; o >>= 1) v += __shfl_xor_sync(0xffffffffu, v, o);
    return v;
}
__device__ __forceinline__ float blockMax(float v, float* red, int nw) {
    int lane = threadIdx.x & 31, w = threadIdx.x >> 5;
    v = warpMaxAll(v);
    if (lane == 0) red[w] = v;
    __syncthreads();
    if (w == 0) {
        float r = (lane < nw) ? red[lane] : -1e30f;
        r = warpMaxAll(r);
        if (lane == 0) red[0] = r;
    }
    __syncthreads();
    float out = red[0];
    __syncthreads();
    return out;
}
__device__ __forceinline__ float blockSum(float v, float* red, int nw) {
    int lane = threadIdx.x & 31, w = threadIdx.x >> 5;
    v = warpSumAll(v);
    if (lane == 0) red[w] = v;
    __syncthreads();
    if (w == 0) {
        float r = (lane < nw) ? red[lane] : 0.f;
        r = warpSumAll(r);
        if (lane == 0) red[0] = r;
    }
    __syncthreads();
    float out = red[0];
    __syncthreads();
    return out;
}

// ---------------------------------------------------------------------------
// Tiled NT-GEMM core: C[m,n] += sum_k A[m,k]*B[n,k], both K-contiguous.
// Shared tiles transposed ([k][m]) for conflict-light LDS.128; FFMA2 inner.
// ---------------------------------------------------------------------------
template <int BM, int BN, int BK, int TM, int TN>
__device__ __forceinline__ void gemm_core(
    const float* __restrict__ A, int lda,
    const float* __restrict__ Bm, int ldb,
    int m0, int n0, int N, int K,
    ull (&acc)[TM][TN / 2])
{
    constexpr int NTX = BN / TN;
    constexpr int THREADS = (BM / TM) * (BN / TN);
    constexpr int K4 = BK / 4;

    __shared__ __align__(16) float As[BK][BM + 4];
    __shared__ __align__(16) float Bs[BK][BN + 4];

    const int tid = threadIdx.x;
    const int tx = tid % NTX;
    const int ty = tid / NTX;

    for (int kt = 0; kt < K; kt += BK) {
        #pragma unroll
        for (int p = 0; p < (BM * K4) / THREADS; ++p) {
            int idx = tid + p * THREADS;
            int row = idx / K4;
            int kq  = (idx % K4) * 4;
            float4 v = *reinterpret_cast<const float4*>(
                A + (size_t)(m0 + row) * lda + kt + kq);
            As[kq + 0][row] = v.x; As[kq + 1][row] = v.y;
            As[kq + 2][row] = v.z; As[kq + 3][row] = v.w;
        }
        #pragma unroll
        for (int p = 0; p < (BN * K4) / THREADS; ++p) {
            int idx = tid + p * THREADS;
            int col = idx / K4;
            int kq  = (idx % K4) * 4;
            int j = n0 + col;
            float4 v = make_float4(0.f, 0.f, 0.f, 0.f);
            if (j < N)
                v = *reinterpret_cast<const float4*>(
                    Bm + (size_t)j * ldb + kt + kq);
            Bs[kq + 0][col] = v.x; Bs[kq + 1][col] = v.y;
            Bs[kq + 2][col] = v.z; Bs[kq + 3][col] = v.w;
        }
        __syncthreads();

        #pragma unroll 8
        for (int k = 0; k < BK; ++k) {
            float a[TM];
            #pragma unroll
            for (int c = 0; c < TM / 4; ++c) {
                float4 t4 = *reinterpret_cast<const float4*>(&As[k][ty * TM + 4 * c]);
                a[4 * c + 0] = t4.x; a[4 * c + 1] = t4.y;
                a[4 * c + 2] = t4.z; a[4 * c + 3] = t4.w;
            }
            ull Bv[TN / 2];
            #pragma unroll
            for (int c = 0; c < TN / 4; ++c) {
                double2 d = *reinterpret_cast<const double2*>(&Bs[k][tx * TN + 4 * c]);
                Bv[2 * c + 0] = __double_as_longlong(d.x);
                Bv[2 * c + 1] = __double_as_longlong(d.y);
            }
            #pragma unroll
            for (int i = 0; i < TM; ++i) {
                ull ad = dup2f(a[i]);
                #pragma unroll
                for (int q = 0; q < TN / 2; ++q)
                    acc[i][q] = ffma2(ad, Bv[q], acc[i][q]);
            }
        }
        __syncthreads();
    }
}

// ---------------------------------------------------------------------------
// Generic GEMM with bias epilogue: C = A @ B^T + bias
// ---------------------------------------------------------------------------
template <int BM, int BN, int BK, int TM, int TN>
__global__ void __launch_bounds__((BM / TM) * (BN / TN), 2)
k_gemm_bias(const float* __restrict__ A, int lda,
            const float* __restrict__ Bm, int ldb,
            const float* __restrict__ bias,
            float* __restrict__ C, int ldc, int N, int K)
{
    ull acc[TM][TN / 2];
    #pragma unroll
    for (int i = 0; i < TM; ++i)
        #pragma unroll
        for (int q = 0; q < TN / 2; ++q) acc[i][q] = 0ull;

    int m0 = blockIdx.y * BM, n0 = blockIdx.x * BN;
    gemm_core<BM, BN, BK, TM, TN>(A, lda, Bm, ldb, m0, n0, N, K, acc);

    int tx = threadIdx.x % (BN / TN), ty = threadIdx.x / (BN / TN);
    #pragma unroll
    for (int i = 0; i < TM; ++i) {
        size_t r = (size_t)(m0 + ty * TM + i);
        #pragma unroll
        for (int q = 0; q < TN / 2; ++q) {
            float2 c2 = unpack2(acc[i][q]);
            int j = n0 + tx * TN + 2 * q;
            if (j < N)     C[r * ldc + j]     = c2.x + bias[j];
            if (j + 1 < N) C[r * ldc + j + 1] = c2.y + bias[j + 1];
        }
    }
}

// ---------------------------------------------------------------------------
// Attention scores GEMM, fused relu(.)·v epilogue.
// rows r = t*B + b of enc[T,B,H];  pre = encW2 + Hh[b,:] + cov[b,t]*u + (b in Hh)
// partial score per j-tile -> g_spart[which][jtile][b*T+t]  (deterministic slot)
// ---------------------------------------------------------------------------
__global__ void __launch_bounds__(256, 2)
k_scores(const float* __restrict__ enc,   // [T,B,H]
         const float* __restrict__ W2,    // row j at j*1536, K-contig
         const float* __restrict__ v,     // [H]
         const float* __restrict__ cov,   // [B,T]
         int which)
{
    ull acc[8][4];
    #pragma unroll
    for (int i = 0; i < 8; ++i)
        #pragma unroll
        for (int q = 0; q < 4; ++q) acc[i][q] = 0ull;

    int m0 = blockIdx.y * 128, n0 = blockIdx.x * 128;
    gemm_core<128, 128, 32, 8, 8>(enc, HH, W2, 3 * HH, m0, n0, HH, HH, acc);

    const float* Hh = g_Hh[which];
    const float* u  = g_u[which];
    float* sp = &g_spart[which][blockIdx.x][0];

    int tx = threadIdx.x % 16, ty = threadIdx.x / 16;
    #pragma unroll
    for (int i = 0; i < 8; ++i) {
        int r = m0 + ty * 8 + i;
        int b = r & (BB - 1);
        int t = r >> 7;
        float covv = cov[b * TT + t];
        const float* HhRow = Hh + b * HH;
        float partial = 0.f;
        #pragma unroll
        for (int q = 0; q < 4; ++q) {
            float2 c2 = unpack2(acc[i][q]);
            int j = n0 + tx * 8 + 2 * q;
            float p0 = c2.x + HhRow[j]     + covv * u[j];
            float p1 = c2.y + HhRow[j + 1] + covv * u[j + 1];
            partial += fmaxf(p0, 0.f) * v[j] + fmaxf(p1, 0.f) * v[j + 1];
        }
        #pragma unroll
        for (int off = 8; off; off >>= 1)
            partial += __shfl_down_sync(0xffffffffu, partial, off, 16);
        if (tx == 0) sp[b * TT + t] = partial;
    }
}

// ---------------------------------------------------------------------------
// Small kernels
// ---------------------------------------------------------------------------
__global__ void k_emb(const int* __restrict__ inputs,
                      const float* __restrict__ emb)
{
    int idx = blockIdx.x * blockDim.x + threadIdx.x;   // B*E = 65536
    int b = idx >> 9, e = idx & 511;
    g_x[b * (EE + HH) + e] = emb[(size_t)inputs[b] * EE + e];
}

__global__ void k_u(const float* __restrict__ cW, const float* __restrict__ cWc,
                    const float* __restrict__ aW, const float* __restrict__ aWc)
{
    const float* W  = blockIdx.x ? aW : cW;
    const float* Wc = blockIdx.x ? aWc : cWc;
    float* u = g_u[blockIdx.x];
    __shared__ float wcS[HH];
    for (int i = threadIdx.x; i < HH; i += blockDim.x) wcS[i] = Wc[i];
    __syncthreads();
    for (int j = threadIdx.x; j < HH; j += blockDim.x) {
        const float* row = W + (size_t)j * (3 * HH) + 2 * HH;   // W3
        float s = 0.f;
        for (int k = 0; k < HH; ++k) s += row[k] * wcS[k];
        u[j] = s;
    }
}

__global__ void k_softmax(const float* __restrict__ covc,
                          const float* __restrict__ cova,
                          float* __restrict__ dout)
{
    int b = blockIdx.x;
    int t = threadIdx.x;          // 512 threads
    __shared__ float red[32];
    #pragma unroll
    for (int w = 0; w < 2; ++w) {
        const float* base = &g_spart[w][0][0];
        int o = b * TT + t;
        float s = base[o] + base[BB * TT + o] + base[2 * BB * TT + o] + base[3 * BB * TT + o];
        float mx = blockMax(s, red, 16);
        float e = expf(s - mx);
        float sum = blockSum(e, red, 16);
        float wgt = e / sum;
        const float* cov = w ? cova : covc;
        dout[(w ? OFF_AW : OFF_CW) + o] = wgt;
        dout[(w ? OFF_ACOV : OFF_CCOV) + o] = cov[o] + wgt;
        __syncthreads();
    }
}

__global__ void k_ctx(const float* __restrict__ code,
                      const float* __restrict__ ast,
                      const float* __restrict__ dout)
{
    int b = blockIdx.x >> 2;
    int hc = blockIdx.x & 3;
    int h = hc * 128 + threadIdx.x;
    __shared__ float wc[TT], wa[TT];
    for (int i = threadIdx.x; i < TT; i += 128) {
        wc[i] = dout[OFF_CW + b * TT + i];
        wa[i] = dout[OFF_AW + b * TT + i];
    }
    __syncthreads();
    const float* cp = code + (size_t)b * HH + h;
    const float* ap = ast  + (size_t)b * HH + h;
    float ac = 0.f, aa = 0.f;
    #pragma unroll 8
    for (int t = 0; t < TT; ++t) {
        ac += wc[t] * cp[(size_t)t * (BB * HH)];
        aa += wa[t] * ap[(size_t)t * (BB * HH)];
    }
    float ctx = 0.5f * (ac + aa);
    g_x[b * (EE + HH) + EE + h] = ctx;
    g_y[b * (2 * HH) + HH + h] = ctx;
}

__global__ void k_gate(const float* __restrict__ h0, float* __restrict__ dout)
{
    int idx = blockIdx.x * blockDim.x + threadIdx.x;   // B*H = 65536
    int b = idx >> 9, h = idx & 511;
    const float* gi = g_gi + b * 3 * HH;
    const float* gh = g_gh + b * 3 * HH;
    float r = 1.f / (1.f + expf(-(gi[h] + gh[h])));
    float z = 1.f / (1.f + expf(-(gi[HH + h] + gh[HH + h])));
    float n = tanhf(gi[2 * HH + h] + r * gh[2 * HH + h]);
    float h1 = (1.f - z) * n + z * h0[idx];
    dout[OFF_H1 + idx] = h1;
    g_y[b * (2 * HH) + h] = h1;
}

__global__ void k_lsm(float* __restrict__ dout)
{
    int b = blockIdx.x;
    float* row = dout + (size_t)b * VOUT;
    __shared__ float red[32];
    float mx = -1e30f;
    for (int i = threadIdx.x; i < VOUT; i += blockDim.x) mx = fmaxf(mx, row[i]);
    mx = blockMax(mx, red, 8);
    float s = 0.f;
    for (int i = threadIdx.x; i < VOUT; i += blockDim.x) s += expf(row[i] - mx);
    s = blockSum(s, red, 8);
    float ls = logf(s);
    for (int i = threadIdx.x; i < VOUT; i += blockDim.x) row[i] = row[i] - mx - ls;
}

// ---------------------------------------------------------------------------
// Launch
// ---------------------------------------------------------------------------
extern "C" void kernel_launch(void* const* d_in, const int* in_sizes, int n_in,
                              void* d_out, int out_size)
{
    (void)in_sizes; (void)n_in; (void)out_size;

    const int*   inp   = (const int*)  d_in[0];
    const float* h0    = (const float*)d_in[1];   // [B,H]
    const float* code  = (const float*)d_in[2];   // [T,B,H]
    const float* ast   = (const float*)d_in[3];
    const float* ccov  = (const float*)d_in[4];   // [B,T]
    const float* acov  = (const float*)d_in[5];
    const float* emb   = (const float*)d_in[6];
    const float* cW    = (const float*)d_in[7];   // [H,3H]
    const float* cb    = (const float*)d_in[8];
    const float* cv    = (const float*)d_in[9];
    const float* cWc   = (const float*)d_in[10];
    const float* aW    = (const float*)d_in[11];
    const float* ab    = (const float*)d_in[12];
    const float* av    = (const float*)d_in[13];
    const float* aWc   = (const float*)d_in[14];
    const float* Wih   = (const float*)d_in[15];  // [3H, E+H]
    const float* Whh   = (const float*)d_in[16];  // [3H, H]
    const float* bih   = (const float*)d_in[17];
    const float* bhh   = (const float*)d_in[18];
    const float* Wout  = (const float*)d_in[19];  // [VOUT, 2H]
    const float* bout  = (const float*)d_in[20];
    float* out = (float*)d_out;

    float *p_x, *p_y, *p_gi, *p_gh, *p_Hh;
    cudaGetSymbolAddress((void**)&p_x,  g_x);
    cudaGetSymbolAddress((void**)&p_y,  g_y);
    cudaGetSymbolAddress((void**)&p_gi, g_gi);
    cudaGetSymbolAddress((void**)&p_gh, g_gh);
    cudaGetSymbolAddress((void**)&p_Hh, g_Hh);

    // embedding gather + rank-1 coverage weights
    k_emb<<<256, 256>>>(inp, emb);
    k_u<<<2, 256>>>(cW, cWc, aW, aWc);

    // Hh = h0 @ W1^T + b_attn   (W1 = W_attn[:, 0:H], row stride 3H)
    k_gemm_bias<64, 64, 32, 4, 4><<<dim3(8, 2), 256>>>(
        h0, HH, cW, 3 * HH, cb, p_Hh, HH, HH, HH);
    k_gemm_bias<64, 64, 32, 4, 4><<<dim3(8, 2), 256>>>(
        h0, HH, aW, 3 * HH, ab, p_Hh + BB * HH, HH, HH, HH);

    // fused attention-score GEMMs (enc @ W2^T, relu·v reduced in epilogue)
    k_scores<<<dim3(4, 512), 256>>>(code, cW + HH, cv, ccov, 0);
    k_scores<<<dim3(4, 512), 256>>>(ast,  aW + HH, av, acov, 1);

    // softmax over T -> cw, aw, ccov_out, acov_out
    k_softmax<<<BB, 512>>>(ccov, acov, out);

    // ctx = 0.5*(cw·code + aw·ast); fill second halves of x and y
    k_ctx<<<BB * 4, 128>>>(code, ast, out);

    // GRU gates
    k_gemm_bias<64, 64, 32, 4, 4><<<dim3(24, 2), 256>>>(
        p_x, EE + HH, Wih, EE + HH, bih, p_gi, 3 * HH, 3 * HH, EE + HH);
    k_gemm_bias<64, 64, 32, 4, 4><<<dim3(24, 2), 256>>>(
        h0, HH, Whh, HH, bhh, p_gh, 3 * HH, 3 * HH, HH);
    k_gate<<<256, 256>>>(h0, out);

    // logits = [h1, ctx] @ W_out^T + b_out, then log-softmax in place
    k_gemm_bias<128, 128, 32, 8, 8><<<dim3((VOUT + 127) / 128, 1), 256>>>(
        p_y, 2 * HH, Wout, 2 * HH, bout, out, VOUT, VOUT, 2 * HH);
    k_lsm<<<BB, 256>>>(out);
}